// round 10
// baseline (speedup 1.0000x reference)
#include <cuda_runtime.h>
#include <cstdint>

// ---------------- problem constants ----------------
#define BB    16
#define PP    512
#define MS    13
#define DD    768
#define KTOT  9216
#define LH    144

// ---------------- GEMM tiling ----------------
#define BM 128
#define BN 256
#define BK 32
#define NTH 256
#define STAGES 3
#define KITERS (KTOT/BK)                   // 288
#define A_TILE_BYTES (BM*BK*4)             // 16384
#define B_TILE_BYTES (BN*BK*4)             // 32768
#define STAGE_BYTES  (A_TILE_BYTES + B_TILE_BYTES)   // 49152
#define DYN_SMEM     (STAGES*STAGE_BYTES)  // 147456

// ---------------- device scratch ----------------
__device__ float g_cvec[BB * DD];
__device__ float g_WT[(size_t)DD * KTOT];            // rna(tf32) W_O^T: [d][k]
__device__ float g_As[(size_t)BB * PP * KTOT];       // masked + rna(tf32) A

// ---------------- helpers ----------------
__device__ __forceinline__ uint32_t smem_u32(const void* p) {
    uint32_t a;
    asm("{ .reg .u64 t; cvta.to.shared.u64 t, %1; cvt.u32.u64 %0, t; }" : "=r"(a) : "l"(p));
    return a;
}
__device__ __forceinline__ float rna_tf32f(float x) {
    uint32_t r;
    asm("cvt.rna.tf32.f32 %0, %1;" : "=r"(r) : "f"(x));
    return __uint_as_float(r);
}
__device__ __forceinline__ void cp16(uint32_t dst, const void* src) {
    asm volatile("cp.async.cg.shared.global [%0], [%1], 16;" :: "r"(dst), "l"(src) : "memory");
}
#define CP_COMMIT()  asm volatile("cp.async.commit_group;" ::: "memory")
#define CP_WAIT1()   asm volatile("cp.async.wait_group 1;" ::: "memory")

#define LDSM_X4(r, a) \
    asm volatile("ldmatrix.sync.aligned.m8n8.x4.shared.b16 {%0,%1,%2,%3}, [%4];" \
                 : "=r"((r)[0]), "=r"((r)[1]), "=r"((r)[2]), "=r"((r)[3]) : "r"(a))

__device__ __forceinline__ void mma_tf32(float* d, const uint32_t* a, const uint32_t* b) {
    asm volatile(
        "mma.sync.aligned.m16n8k8.row.col.f32.tf32.tf32.f32 "
        "{%0,%1,%2,%3}, {%4,%5,%6,%7}, {%8,%9}, {%0,%1,%2,%3};"
        : "+f"(d[0]), "+f"(d[1]), "+f"(d[2]), "+f"(d[3])
        : "r"(a[0]), "r"(a[1]), "r"(a[2]), "r"(a[3]), "r"(b[0]), "r"(b[1]));
}

// XOR swizzle: 16B granule g within a 128B row, keyed by row low bits
__device__ __forceinline__ uint32_t swzg(int row, int g) {
    return (uint32_t)(row * 128 + (((g ^ row) & 7) << 4));
}

// ---------------- prep kernels ----------------
__global__ void prep_cvec(const float* __restrict__ mlp_mask, const float* __restrict__ attn_mask,
                          const float* __restrict__ mlp_constants, const float* __restrict__ attn_constants,
                          const float* __restrict__ post_bias) {
    int b = blockIdx.x, d = threadIdx.x;
    float acc = post_bias[d];
#pragma unroll
    for (int m = 0; m < MS; m++)
        acc += (1.0f - mlp_mask[b * MS + m]) * mlp_constants[m * DD + d];
    for (int lh = 0; lh < LH; lh++)
        acc += (1.0f - attn_mask[b * LH + lh]) * attn_constants[lh * DD + d];
    g_cvec[b * DD + d] = acc;
}

// g_WT[d][k] = rna_tf32(W_O[k][d])
__global__ void prep_wt(const float* __restrict__ W_O) {
    __shared__ float tile[32][33];
    int kt = blockIdx.x * 32, dt = blockIdx.y * 32;
    int tx = threadIdx.x & 31, ty = threadIdx.x >> 5;   // 32x8
#pragma unroll
    for (int i = 0; i < 4; i++)
        tile[ty + 8 * i][tx] = rna_tf32f(W_O[(size_t)(kt + ty + 8 * i) * DD + dt + tx]);
    __syncthreads();
#pragma unroll
    for (int i = 0; i < 4; i++)
        g_WT[(size_t)(dt + ty + 8 * i) * KTOT + kt + tx] = tile[tx][ty + 8 * i];
}

// g_As = rna_tf32(attn_cache * attn_mask[b, k/64])
__global__ void prep_as(const float* __restrict__ attn_cache, const float* __restrict__ attn_mask) {
    size_t f = (size_t)blockIdx.x * blockDim.x + threadIdx.x;   // float4 index
    int k4 = (int)(f % (KTOT / 4));
    size_t bp = f / (KTOT / 4);
    int b = (int)(bp >> 9);
    float mk = __ldg(&attn_mask[b * LH + (k4 >> 4)]);
    float4 v = ((const float4*)attn_cache)[f];
    float4 r;
    r.x = rna_tf32f(v.x * mk); r.y = rna_tf32f(v.y * mk);
    r.z = rna_tf32f(v.z * mk); r.w = rna_tf32f(v.w * mk);
    ((float4*)g_As)[f] = r;
}

// ---------------- main GEMM (mma.sync tf32, ldmatrix fragments) ----------------
__global__ void __launch_bounds__(NTH)
gemm_kernel(const float* __restrict__ mlp_cache,
            const float* __restrict__ mlp_mask,
            float* __restrict__ out) {
    extern __shared__ char smem[];
    const uint32_t dyn = smem_u32(smem);

    const int tid  = threadIdx.x;
    const int wid  = tid >> 5;
    const int lane = tid & 31;
    const int b  = blockIdx.z;
    const int p0 = blockIdx.y * BM;
    const int d0 = blockIdx.x * BN;

    // producers: A row = tid>>1 (128 rows), 4 granules; B row = tid (256 rows), 8 granules
    const int a_row = tid >> 1;
    const int a_g0  = (tid & 1) * 4;
    const float* gA = g_As + (size_t)(b * PP + p0 + a_row) * KTOT;
    const float* gB = g_WT + (size_t)(d0 + tid) * KTOT;

    // warp tiling: 2(m) x 4(n) warps, each 64(m) x 64(n)
    const int wm = (wid >> 2) * 64;
    const int wn = (wid & 3) * 64;

    const int gid = lane >> 2;   // 0..7
    const int tig = lane & 3;    // 0..3

    // ldmatrix address components
    const int a_lrow  = (lane & 7) + (((lane >> 3) & 1) << 3);  // 0..15
    const int a_lghalf = lane >> 4;                             // 0/1
    const int b_lrow  = lane & 7;
    const int b_lnf   = (lane >> 4) & 1;                        // nf within pair
    const int b_lghalf = (lane >> 3) & 1;

    float acc[4][8][4];
#pragma unroll
    for (int mf = 0; mf < 4; mf++)
#pragma unroll
        for (int nf = 0; nf < 8; nf++)
#pragma unroll
            for (int j = 0; j < 4; j++) acc[mf][nf][j] = 0.0f;

    // ---- prologue: stages 0,1 ----
#pragma unroll
    for (int s = 0; s < 2; s++) {
        const uint32_t aB = dyn + s * STAGE_BYTES;
        const uint32_t bB = aB + A_TILE_BYTES;
        const int k0 = s * BK;
#pragma unroll
        for (int g = 0; g < 4; g++)
            cp16(aB + swzg(a_row, a_g0 + g), gA + k0 + (a_g0 + g) * 4);
#pragma unroll
        for (int g = 0; g < 8; g++)
            cp16(bB + swzg(tid, g), gB + k0 + g * 4);
        CP_COMMIT();
    }

    // ---- main loop ----
    for (int it = 0; it < KITERS; it++) {
        CP_WAIT1();
        __syncthreads();

        const int s = it % STAGES;
        const uint32_t aB = dyn + s * STAGE_BYTES;
        const uint32_t bB = aB + A_TILE_BYTES;

        if (it + 2 < KITERS) {
            const int s2 = (it + 2) % STAGES;
            const uint32_t aB2 = dyn + s2 * STAGE_BYTES;
            const uint32_t bB2 = aB2 + A_TILE_BYTES;
            const int k0 = (it + 2) * BK;
#pragma unroll
            for (int g = 0; g < 4; g++)
                cp16(aB2 + swzg(a_row, a_g0 + g), gA + k0 + (a_g0 + g) * 4);
#pragma unroll
            for (int g = 0; g < 8; g++)
                cp16(bB2 + swzg(tid, g), gB + k0 + g * 4);
        }
        CP_COMMIT();

#pragma unroll
        for (int ks = 0; ks < 4; ks++) {
            // A fragments: 4 m-frags, one ldmatrix.x4 each
            uint32_t af[4][4];
#pragma unroll
            for (int mf = 0; mf < 4; mf++) {
                const int row = wm + mf * 16 + a_lrow;
                LDSM_X4(af[mf], aB + swzg(row, ks * 2 + a_lghalf));
            }
            // B fragments: 8 n-frags as 4 pair-loads
            uint32_t bf[8][2];
#pragma unroll
            for (int nfp = 0; nfp < 4; nfp++) {
                const int row = wn + (nfp * 2 + b_lnf) * 8 + b_lrow;
                uint32_t r4[4];
                LDSM_X4(r4, bB + swzg(row, ks * 2 + b_lghalf));
                bf[2 * nfp + 0][0] = r4[0]; bf[2 * nfp + 0][1] = r4[1];
                bf[2 * nfp + 1][0] = r4[2]; bf[2 * nfp + 1][1] = r4[3];
            }
#pragma unroll
            for (int mf = 0; mf < 4; mf++)
#pragma unroll
                for (int nf = 0; nf < 8; nf++)
                    mma_tf32(acc[mf][nf], af[mf], bf[nf]);
        }
    }

    // ---- epilogue: + cvec + mlp streams, straight from C fragments ----
    float w[MS];
#pragma unroll
    for (int m = 0; m < MS; m++) w[m] = mlp_mask[b * MS + m];

    float2 cv[8];
#pragma unroll
    for (int nf = 0; nf < 8; nf++)
        cv[nf] = *(const float2*)(g_cvec + b * DD + d0 + wn + nf * 8 + 2 * tig);

#pragma unroll
    for (int mf = 0; mf < 4; mf++) {
#pragma unroll
        for (int hi = 0; hi < 2; hi++) {
            const int p = p0 + wm + mf * 16 + hi * 8 + gid;
            const float* mbase = mlp_cache + ((size_t)(b * PP + p) * MS) * DD + d0 + wn + 2 * tig;
            float* obase = out + (size_t)(b * PP + p) * DD + d0 + wn + 2 * tig;
#pragma unroll
            for (int nf = 0; nf < 8; nf++) {
                float2 v;
                v.x = acc[mf][nf][hi * 2 + 0] + cv[nf].x;
                v.y = acc[mf][nf][hi * 2 + 1] + cv[nf].y;
#pragma unroll
                for (int m = 0; m < MS; m++) {
                    const float2 mv = *(const float2*)(mbase + (size_t)m * DD + nf * 8);
                    v.x += w[m] * mv.x;
                    v.y += w[m] * mv.y;
                }
                *(float2*)(obase + nf * 8) = v;
            }
        }
    }
}

// ---------------- launch ----------------
extern "C" void kernel_launch(void* const* d_in, const int* in_sizes, int n_in,
                              void* d_out, int out_size) {
    const float* mlp_cache      = (const float*)d_in[0];
    const float* attn_cache     = (const float*)d_in[1];
    const float* mlp_mask       = (const float*)d_in[2];
    const float* attn_mask      = (const float*)d_in[3];
    const float* mlp_constants  = (const float*)d_in[4];
    const float* attn_constants = (const float*)d_in[5];
    const float* W_O            = (const float*)d_in[6];
    const float* post_bias      = (const float*)d_in[7];
    float* out = (float*)d_out;

    static bool attr_done = false;
    if (!attr_done) {
        cudaFuncSetAttribute(gemm_kernel, cudaFuncAttributeMaxDynamicSharedMemorySize, DYN_SMEM);
        attr_done = true;
    }

    prep_cvec<<<BB, DD>>>(mlp_mask, attn_mask, mlp_constants, attn_constants, post_bias);
    {
        dim3 gw(KTOT / 32, DD / 32);
        prep_wt<<<gw, 256>>>(W_O);
    }
    {
        size_t nf4 = (size_t)BB * PP * KTOT / 4;
        prep_as<<<(unsigned)(nf4 / 256), 256>>>(attn_cache, attn_mask);
    }
    {
        dim3 grid(DD / BN, PP / BM, BB);   // (3, 4, 16)
        gemm_kernel<<<grid, NTH, DYN_SMEM>>>(mlp_cache, mlp_mask, out);
    }
}

// round 12
// speedup vs baseline: 1.5698x; 1.5698x over previous
#include <cuda_runtime.h>
#include <cstdint>

// ---------------- problem constants ----------------
#define BB    16
#define PP    512
#define MS    13
#define DD    768
#define KTOT  9216
#define LH    144

// ---------------- GEMM tiling ----------------
#define BM 128
#define BN 128
#define BK 32
#define NTH 256
#define STAGES 3
#define KITERS (KTOT/BK)                   // 288
#define A_TILE_BYTES (BM*BK*4)             // 16384
#define B_TILE_BYTES (BN*BK*4)             // 16384
#define STAGE_BYTES  (A_TILE_BYTES + B_TILE_BYTES)   // 32768
#define DYN_SMEM     (STAGES*STAGE_BYTES)  // 98304

// ---------------- device scratch ----------------
__device__ float g_cvec[BB * DD];
__device__ float g_WT[(size_t)DD * KTOT];            // rna(tf32) W_O^T: [d][k]
__device__ float g_As[(size_t)BB * PP * KTOT];       // masked + rna(tf32) A

// ---------------- helpers ----------------
__device__ __forceinline__ uint32_t smem_u32(const void* p) {
    uint32_t a;
    asm("{ .reg .u64 t; cvta.to.shared.u64 t, %1; cvt.u32.u64 %0, t; }" : "=r"(a) : "l"(p));
    return a;
}
__device__ __forceinline__ float rna_tf32f(float x) {
    uint32_t r;
    asm("cvt.rna.tf32.f32 %0, %1;" : "=r"(r) : "f"(x));
    return __uint_as_float(r);
}
__device__ __forceinline__ void cp16(uint32_t dst, const void* src) {
    asm volatile("cp.async.cg.shared.global [%0], [%1], 16;" :: "r"(dst), "l"(src) : "memory");
}
#define CP_COMMIT()  asm volatile("cp.async.commit_group;" ::: "memory")
#define CP_WAIT1()   asm volatile("cp.async.wait_group 1;" ::: "memory")

#define LDSM_X4(r, a) \
    asm volatile("ldmatrix.sync.aligned.m8n8.x4.shared.b16 {%0,%1,%2,%3}, [%4];" \
                 : "=r"((r)[0]), "=r"((r)[1]), "=r"((r)[2]), "=r"((r)[3]) : "r"(a))

__device__ __forceinline__ void mma_tf32(float* d, const uint32_t* a, const uint32_t* b) {
    asm volatile(
        "mma.sync.aligned.m16n8k8.row.col.f32.tf32.tf32.f32 "
        "{%0,%1,%2,%3}, {%4,%5,%6,%7}, {%8,%9}, {%0,%1,%2,%3};"
        : "+f"(d[0]), "+f"(d[1]), "+f"(d[2]), "+f"(d[3])
        : "r"(a[0]), "r"(a[1]), "r"(a[2]), "r"(a[3]), "r"(b[0]), "r"(b[1]));
}

// XOR swizzle: 16B granule g within a 128B row, keyed by row low bits
__device__ __forceinline__ uint32_t swzg(int row, int g) {
    return (uint32_t)(row * 128 + (((g ^ row) & 7) << 4));
}

// ---------------- prep kernels ----------------
__global__ void prep_cvec(const float* __restrict__ mlp_mask, const float* __restrict__ attn_mask,
                          const float* __restrict__ mlp_constants, const float* __restrict__ attn_constants,
                          const float* __restrict__ post_bias) {
    int b = blockIdx.x, d = threadIdx.x;
    float acc = post_bias[d];
#pragma unroll
    for (int m = 0; m < MS; m++)
        acc += (1.0f - mlp_mask[b * MS + m]) * mlp_constants[m * DD + d];
    for (int lh = 0; lh < LH; lh++)
        acc += (1.0f - attn_mask[b * LH + lh]) * attn_constants[lh * DD + d];
    g_cvec[b * DD + d] = acc;
}

// g_WT[d][k] = rna_tf32(W_O[k][d])
__global__ void prep_wt(const float* __restrict__ W_O) {
    __shared__ float tile[32][33];
    int kt = blockIdx.x * 32, dt = blockIdx.y * 32;
    int tx = threadIdx.x & 31, ty = threadIdx.x >> 5;   // 32x8
#pragma unroll
    for (int i = 0; i < 4; i++)
        tile[ty + 8 * i][tx] = rna_tf32f(W_O[(size_t)(kt + ty + 8 * i) * DD + dt + tx]);
    __syncthreads();
#pragma unroll
    for (int i = 0; i < 4; i++)
        g_WT[(size_t)(dt + ty + 8 * i) * KTOT + kt + tx] = tile[tx][ty + 8 * i];
}

// g_As = rna_tf32(attn_cache * attn_mask[b, k/64])
__global__ void prep_as(const float* __restrict__ attn_cache, const float* __restrict__ attn_mask) {
    size_t f = (size_t)blockIdx.x * blockDim.x + threadIdx.x;   // float4 index
    int k4 = (int)(f % (KTOT / 4));
    size_t bp = f / (KTOT / 4);
    int b = (int)(bp >> 9);
    float mk = __ldg(&attn_mask[b * LH + (k4 >> 4)]);
    float4 v = ((const float4*)attn_cache)[f];
    float4 r;
    r.x = rna_tf32f(v.x * mk); r.y = rna_tf32f(v.y * mk);
    r.z = rna_tf32f(v.z * mk); r.w = rna_tf32f(v.w * mk);
    ((float4*)g_As)[f] = r;
}

// ---------------- main GEMM: 128x128 CTA, 8 warps of 64x32, 2 CTAs/SM ----------------
__global__ void __launch_bounds__(NTH, 2)
gemm_kernel(const float* __restrict__ mlp_cache,
            const float* __restrict__ mlp_mask,
            float* __restrict__ out) {
    extern __shared__ char smem[];
    const uint32_t dyn = smem_u32(smem);

    const int tid  = threadIdx.x;
    const int wid  = tid >> 5;
    const int lane = tid & 31;
    const int b  = blockIdx.z;
    const int p0 = blockIdx.y * BM;
    const int d0 = blockIdx.x * BN;

    // producers: both tiles 128 rows x 32 floats; thread owns row tid>>1, granules (tid&1)*4..+3
    const int prow = tid >> 1;
    const int pg0  = (tid & 1) * 4;
    const float* gA = g_As + (size_t)(b * PP + p0 + prow) * KTOT;
    const float* gB = g_WT + (size_t)(d0 + prow) * KTOT;

    // warps: 2(m) x 4(n), warp tile 64(m) x 32(n)
    const int wm = (wid >> 2) * 64;
    const int wn = (wid & 3) * 32;

    const int gid = lane >> 2;
    const int tig = lane & 3;

    // ldmatrix lane addressing (verified R9/R10: identical rel_err)
    const int a_lrow   = (lane & 7) + (((lane >> 3) & 1) << 3);
    const int a_lghalf = lane >> 4;
    const int b_lrow   = lane & 7;
    const int b_lnf    = (lane >> 4) & 1;
    const int b_lghalf = (lane >> 3) & 1;

    float acc[4][4][4];   // 4 m-frags x 4 n-frags x 4 = 64 regs
#pragma unroll
    for (int mf = 0; mf < 4; mf++)
#pragma unroll
        for (int nf = 0; nf < 4; nf++)
#pragma unroll
            for (int j = 0; j < 4; j++) acc[mf][nf][j] = 0.0f;

    // ---- prologue: stages 0,1 ----
#pragma unroll
    for (int s = 0; s < 2; s++) {
        const uint32_t aB = dyn + s * STAGE_BYTES;
        const uint32_t bB = aB + A_TILE_BYTES;
        const int k0 = s * BK;
#pragma unroll
        for (int g = 0; g < 4; g++) {
            cp16(aB + swzg(prow, pg0 + g), gA + k0 + (pg0 + g) * 4);
            cp16(bB + swzg(prow, pg0 + g), gB + k0 + (pg0 + g) * 4);
        }
        CP_COMMIT();
    }

    // ---- main loop ----
    for (int it = 0; it < KITERS; it++) {
        CP_WAIT1();
        __syncthreads();

        const int s = it % STAGES;
        const uint32_t aB = dyn + s * STAGE_BYTES;
        const uint32_t bB = aB + A_TILE_BYTES;

        if (it + 2 < KITERS) {
            const int s2 = (it + 2) % STAGES;
            const uint32_t aB2 = dyn + s2 * STAGE_BYTES;
            const uint32_t bB2 = aB2 + A_TILE_BYTES;
            const int k0 = (it + 2) * BK;
#pragma unroll
            for (int g = 0; g < 4; g++) {
                cp16(aB2 + swzg(prow, pg0 + g), gA + k0 + (pg0 + g) * 4);
                cp16(bB2 + swzg(prow, pg0 + g), gB + k0 + (pg0 + g) * 4);
            }
        }
        CP_COMMIT();

#pragma unroll
        for (int ks = 0; ks < 4; ks++) {
            // A fragments: 4 m-frags
            uint32_t af[4][4];
#pragma unroll
            for (int mf = 0; mf < 4; mf++) {
                const int row = wm + mf * 16 + a_lrow;
                LDSM_X4(af[mf], aB + swzg(row, ks * 2 + a_lghalf));
            }
            // B fragments: 4 n-frags as 2 pair-loads
            uint32_t bf[4][2];
#pragma unroll
            for (int nfp = 0; nfp < 2; nfp++) {
                const int row = wn + (nfp * 2 + b_lnf) * 8 + b_lrow;
                uint32_t r4[4];
                LDSM_X4(r4, bB + swzg(row, ks * 2 + b_lghalf));
                bf[2 * nfp + 0][0] = r4[0]; bf[2 * nfp + 0][1] = r4[1];
                bf[2 * nfp + 1][0] = r4[2]; bf[2 * nfp + 1][1] = r4[3];
            }
#pragma unroll
            for (int mf = 0; mf < 4; mf++)
#pragma unroll
                for (int nf = 0; nf < 4; nf++)
                    mma_tf32(acc[mf][nf], af[mf], bf[nf]);
        }
    }

    // ---- epilogue: + cvec + mlp streams ----
    float w[MS];
#pragma unroll
    for (int m = 0; m < MS; m++) w[m] = mlp_mask[b * MS + m];

    float2 cv[4];
#pragma unroll
    for (int nf = 0; nf < 4; nf++)
        cv[nf] = *(const float2*)(g_cvec + b * DD + d0 + wn + nf * 8 + 2 * tig);

#pragma unroll
    for (int mf = 0; mf < 4; mf++) {
#pragma unroll
        for (int hi = 0; hi < 2; hi++) {
            const int p = p0 + wm + mf * 16 + hi * 8 + gid;
            const float* mbase = mlp_cache + ((size_t)(b * PP + p) * MS) * DD + d0 + wn + 2 * tig;
            float* obase = out + (size_t)(b * PP + p) * DD + d0 + wn + 2 * tig;
#pragma unroll
            for (int nf = 0; nf < 4; nf++) {
                float2 v;
                v.x = acc[mf][nf][hi * 2 + 0] + cv[nf].x;
                v.y = acc[mf][nf][hi * 2 + 1] + cv[nf].y;
#pragma unroll
                for (int m = 0; m < MS; m++) {
                    const float2 mv = *(const float2*)(mbase + (size_t)m * DD + nf * 8);
                    v.x += w[m] * mv.x;
                    v.y += w[m] * mv.y;
                }
                *(float2*)(obase + nf * 8) = v;
            }
        }
    }
}

// ---------------- launch ----------------
extern "C" void kernel_launch(void* const* d_in, const int* in_sizes, int n_in,
                              void* d_out, int out_size) {
    const float* mlp_cache      = (const float*)d_in[0];
    const float* attn_cache     = (const float*)d_in[1];
    const float* mlp_mask       = (const float*)d_in[2];
    const float* attn_mask      = (const float*)d_in[3];
    const float* mlp_constants  = (const float*)d_in[4];
    const float* attn_constants = (const float*)d_in[5];
    const float* W_O            = (const float*)d_in[6];
    const float* post_bias      = (const float*)d_in[7];
    float* out = (float*)d_out;

    static bool attr_done = false;
    if (!attr_done) {
        cudaFuncSetAttribute(gemm_kernel, cudaFuncAttributeMaxDynamicSharedMemorySize, DYN_SMEM);
        attr_done = true;
    }

    prep_cvec<<<BB, DD>>>(mlp_mask, attn_mask, mlp_constants, attn_constants, post_bias);
    {
        dim3 gw(KTOT / 32, DD / 32);
        prep_wt<<<gw, 256>>>(W_O);
    }
    {
        size_t nf4 = (size_t)BB * PP * KTOT / 4;
        prep_as<<<(unsigned)(nf4 / 256), 256>>>(attn_cache, attn_mask);
    }
    {
        dim3 grid(DD / BN, PP / BM, BB);   // (6, 4, 16)
        gemm_kernel<<<grid, NTH, DYN_SMEM>>>(mlp_cache, mlp_mask, out);
    }
}